// round 16
// baseline (speedup 1.0000x reference)
#include <cuda_runtime.h>
#include <cuda_bf16.h>
#include <cstdint>

// ---------------- problem constants ----------------
#define B_  16
#define H_  32
#define W_  64
#define WH  33            // W/2+1
#define C_  768
#define NBLK 4
#define BS_ 192           // C/NBLK
#define P_  (B_*H_*WH)    // 16896 frequency positions
#define NKC (WH*C_)       // 25344
#define NTOK (B_*H_*W_)   // 32768 spatial tokens

#define SC_ORTHO 0.0220970869120796f   // 1/sqrt(2048)

// ---------------- scratch (bf16 freq-domain data path) ----------------
__device__ __nv_bfloat16 g_xr[(size_t)P_ * C_];
__device__ __nv_bfloat16 g_xi[(size_t)P_ * C_];
__device__ __nv_bfloat16 g_r1[(size_t)P_ * C_];
__device__ __nv_bfloat16 g_i1[(size_t)P_ * C_];
__device__ __nv_bfloat16 g_r2[(size_t)P_ * C_];
__device__ __nv_bfloat16 g_i2[(size_t)P_ * C_];

// pre-split operands for bias GEMM (accessed ONLY from device code)
__device__ __nv_bfloat16 g_Xhi[(size_t)NTOK * C_];
__device__ __nv_bfloat16 g_Xlo[(size_t)NTOK * C_];
__device__ __nv_bfloat16 g_Whi[(size_t)C_ * C_];
__device__ __nv_bfloat16 g_Wlo[(size_t)C_ * C_];

// pre-split 64x64 DFT operator matrices (bf16 hi/lo)
__device__ __nv_bfloat16 g_Ahf_h[4096], g_Ahf_l[4096];   // H fwd (scaled)
__device__ __nv_bfloat16 g_Ahi_h[4096], g_Ahi_l[4096];   // H inv
__device__ __nv_bfloat16 g_Awf_h[4096], g_Awf_l[4096];   // W fwd (k=0..31)
__device__ __nv_bfloat16 g_Awi_h[4096], g_Awi_l[4096];   // W inv (weights folded)

// =====================================================================
// portable tensor-core helpers
// =====================================================================
__device__ __forceinline__ uint32_t smem_u32(const void* p) {
    uint32_t a;
    asm("{ .reg .u64 t; cvta.to.shared.u64 t, %1; cvt.u32.u64 %0, t; }" : "=r"(a) : "l"(p));
    return a;
}
__device__ __forceinline__ void mma_bf16(float* d, const uint32_t* a, const uint32_t* b) {
    asm volatile("mma.sync.aligned.m16n8k16.row.col.f32.bf16.bf16.f32 "
        "{%0,%1,%2,%3}, {%4,%5,%6,%7}, {%8,%9}, {%0,%1,%2,%3};"
        : "+f"(d[0]), "+f"(d[1]), "+f"(d[2]), "+f"(d[3])
        : "r"(a[0]), "r"(a[1]), "r"(a[2]), "r"(a[3]), "r"(b[0]), "r"(b[1]));
}
__device__ __forceinline__ void ldsm_x4(uint32_t* r, uint32_t addr) {
    asm volatile("ldmatrix.sync.aligned.m8n8.x4.shared.b16 {%0,%1,%2,%3}, [%4];"
        : "=r"(r[0]), "=r"(r[1]), "=r"(r[2]), "=r"(r[3]) : "r"(addr));
}
__device__ __forceinline__ void ldsm_x2(uint32_t* r, uint32_t addr) {
    asm volatile("ldmatrix.sync.aligned.m8n8.x2.shared.b16 {%0,%1}, [%2];"
        : "=r"(r[0]), "=r"(r[1]) : "r"(addr));
}
__device__ __forceinline__ void ldsm_x2_t(uint32_t* r, uint32_t addr) {
    asm volatile("ldmatrix.sync.aligned.m8n8.x2.trans.shared.b16 {%0,%1}, [%2];"
        : "=r"(r[0]), "=r"(r[1]) : "r"(addr));
}
__device__ __forceinline__ void cp_async16(uint32_t dst, const void* src) {
    asm volatile("cp.async.ca.shared.global [%0], [%1], 16;" :: "r"(dst), "l"(src));
}
#define CP_COMMIT() asm volatile("cp.async.commit_group;" ::: "memory")
#define CP_WAIT0()  asm volatile("cp.async.wait_group 0;" ::: "memory")

__device__ __forceinline__ void split4(float4 v, __nv_bfloat16* h, __nv_bfloat16* l) {
    float a[4] = {v.x, v.y, v.z, v.w};
    #pragma unroll
    for (int q = 0; q < 4; q++) {
        h[q] = __float2bfloat16(a[q]);
        l[q] = __float2bfloat16(a[q] - __bfloat162float(h[q]));
    }
}
__device__ __forceinline__ void cvt4(float4 v, __nv_bfloat16* h) {
    h[0] = __float2bfloat16(v.x);
    h[1] = __float2bfloat16(v.y);
    h[2] = __float2bfloat16(v.z);
    h[3] = __float2bfloat16(v.w);
}
__device__ __forceinline__ void split1(float v, __nv_bfloat16& h, __nv_bfloat16& l) {
    h = __float2bfloat16(v);
    l = __float2bfloat16(v - __bfloat162float(h));
}
__device__ __forceinline__ uint32_t pack_bf2(float a, float b) {
    __nv_bfloat162 t = __floats2bfloat162_rn(a, b);
    return *(uint32_t*)&t;
}

// =====================================================================
__global__ void init_tables()
{
    int idx = blockIdx.x * blockDim.x + threadIdx.x;
    for (int i = idx; i < 4096; i += gridDim.x * blockDim.x) {
        int r = i >> 6, q = i & 63;
        {
            float s, c;
            sincospif((float)((r & 31) * (q & 31)) / 16.0f, &s, &c);
            float v;
            if (r < 32)  v = (q < 32) ? c : s;
            else         v = (q < 32) ? -s : c;
            split1(v * SC_ORTHO, g_Ahf_h[i], g_Ahf_l[i]);
        }
        {
            float s, c;
            sincospif((float)((r & 31) * (q & 31)) / 16.0f, &s, &c);
            float v;
            if (r < 32)  v = (q < 32) ? c : -s;
            else         v = (q < 32) ? s : c;
            split1(v, g_Ahi_h[i], g_Ahi_l[i]);
        }
        {
            float s, c;
            sincospif((float)((r & 31) * q) / 32.0f, &s, &c);
            float v = (r < 32) ? c : -s;
            split1(v, g_Awf_h[i], g_Awf_l[i]);
        }
        {
            float v;
            if (q == 0) {
                v = SC_ORTHO;
            } else if (q < 32) {
                float s, c;
                sincospif((float)(q * r) / 32.0f, &s, &c);
                v = 2.f * SC_ORTHO * c;
            } else if (q == 32) {
                v = (r & 1) ? -SC_ORTHO : SC_ORTHO;
            } else {
                int k = q - 32;
                float s, c;
                sincospif((float)(k * r) / 32.0f, &s, &c);
                v = -2.f * SC_ORTHO * s;
            }
            split1(v, g_Awi_h[i], g_Awi_l[i]);
        }
    }
}

// =====================================================================
// fused pre-split convert: X then W (device-global destinations)
// =====================================================================
#define NXQ ((NTOK * C_) / 4)     // 6291456 quads for X
#define NWQ ((C_ * C_) / 4)       // 147456 quads for W

__global__ __launch_bounds__(256) void convert_xw(
    const float* __restrict__ xs, const float* __restrict__ ws)
{
    int qidx = blockIdx.x * 256 + threadIdx.x;
    if (qidx < NXQ) {
        int i = qidx * 4;
        float4 v = *(const float4*)&xs[i];
        __nv_bfloat16 h[4], l[4];
        split4(v, h, l);
        *(uint2*)&g_Xhi[i] = *(uint2*)h;
        *(uint2*)&g_Xlo[i] = *(uint2*)l;
    } else if (qidx - NXQ < NWQ) {
        int i = (qidx - NXQ) * 4;
        float4 v = *(const float4*)&ws[i];
        __nv_bfloat16 h[4], l[4];
        split4(v, h, l);
        *(uint2*)&g_Whi[i] = *(uint2*)h;
        *(uint2*)&g_Wlo[i] = *(uint2*)l;
    }
}

// =====================================================================
// bias GEMM: out[m,c] = sum_k X[m,k]*W[c,k] + bb[c]
// pre-split bf16 global operands, cp.async 2-stage pipeline, 3-term MMA.
// =====================================================================
#define TBM 128
#define TBN 128
#define TBK 32
#define KPAD (TBK + 8)                 // 40 halfs = 80B row stride
#define BARR 10240                     // 128*40*2 bytes per sub-array
#define BSTAGE (4 * BARR)              // Ahi,Alo,Bhi,Blo = 40960
#define NKIT (C_ / TBK)                // 24

__global__ __launch_bounds__(256) void bias_mma(
    const float* __restrict__ bb, float* __restrict__ out)
{
    extern __shared__ char dsm[];
    uint32_t sb = smem_u32(dsm);

    int tid = threadIdx.x;
    int wid = tid >> 5, lane = tid & 31;
    int wm = wid >> 2, wn = wid & 3;
    int m0 = blockIdx.y * TBM, n0 = blockIdx.x * TBN;

    float acc[4][4][4] = {};

    int aRow = lane & 15, aKoff = (lane >> 4) * 8;
    int bRow = lane & 7,  bKoff = ((lane >> 3) & 1) * 8;

    // prefetch one k-chunk into stage st: 4 arrays x 128 rows x 4 chunks(16B), 8/thread
    auto prefetch = [&](int kt, int st) {
        #pragma unroll
        for (int it = 0; it < 8; it++) {
            int lin = tid + 256 * it;
            int arr = lin >> 9;
            int rem = lin & 511;
            int r = rem >> 2, ch = (rem & 3) * 8;
            const __nv_bfloat16* base = (arr == 0) ? g_Xhi : (arr == 1) ? g_Xlo
                                      : (arr == 2) ? g_Whi : g_Wlo;
            int grow = (arr < 2) ? (m0 + r) : (n0 + r);
            const __nv_bfloat16* src = base + (size_t)grow * C_ + kt * TBK + ch;
            uint32_t dst = sb + st * BSTAGE + arr * BARR + (r * KPAD + ch) * 2;
            cp_async16(dst, src);
        }
    };

    prefetch(0, 0);
    CP_COMMIT();

    int cur = 0;
    for (int kt = 0; kt < NKIT; kt++) {
        CP_WAIT0();
        __syncthreads();
        if (kt + 1 < NKIT) {
            prefetch(kt + 1, cur ^ 1);
            CP_COMMIT();
        }
        uint32_t base = sb + cur * BSTAGE;
        #pragma unroll
        for (int s = 0; s < 2; s++) {
            int k0 = s * 16;
            uint32_t a_hi[4][4], a_lo[4][4], b_hi[4][2], b_lo[4][2];
            #pragma unroll
            for (int i = 0; i < 4; i++) {
                int row = wm * 64 + i * 16 + aRow;
                uint32_t off = (row * KPAD + k0 + aKoff) * 2;
                ldsm_x4(a_hi[i], base + off);
                ldsm_x4(a_lo[i], base + BARR + off);
            }
            #pragma unroll
            for (int j = 0; j < 4; j++) {
                int row = wn * 32 + j * 8 + bRow;
                uint32_t off = (row * KPAD + k0 + bKoff) * 2;
                ldsm_x2(b_hi[j], base + 2 * BARR + off);
                ldsm_x2(b_lo[j], base + 3 * BARR + off);
            }
            #pragma unroll
            for (int i = 0; i < 4; i++)
                #pragma unroll
                for (int j = 0; j < 4; j++) {
                    mma_bf16(acc[i][j], a_hi[i], b_hi[j]);
                    mma_bf16(acc[i][j], a_hi[i], b_lo[j]);
                    mma_bf16(acc[i][j], a_lo[i], b_hi[j]);
                }
        }
        cur ^= 1;
    }

    int group = lane >> 2, qid = lane & 3;
    #pragma unroll
    for (int i = 0; i < 4; i++) {
        #pragma unroll
        for (int j = 0; j < 4; j++) {
            int col = n0 + wn * 32 + j * 8 + qid * 2;
            float b0 = bb[col], b1 = bb[col + 1];
            int r0 = m0 + wm * 64 + i * 16 + group;
            float2 v0 = {acc[i][j][0] + b0, acc[i][j][1] + b1};
            float2 v1 = {acc[i][j][2] + b0, acc[i][j][3] + b1};
            *(float2*)&out[(size_t)r0 * C_ + col]       = v0;
            *(float2*)&out[(size_t)(r0 + 8) * C_ + col] = v1;
        }
    }
}

// =====================================================================
// FFT-as-GEMM kernels: C[64, N] = A(64x64, split 2-term) @ B[64, N] (bf16)
// =====================================================================
#define FA_STRIDE 72
#define FB_STRIDE 136

// ---- H-direction DFT (dir 0 = fwd g_r1/g_i1 -> g_xr/g_xi, dir 1 = inv g_r2/g_i2 -> g_xr/g_xi)
__global__ __launch_bounds__(256) void fft_h_mma(int dir)
{
    __shared__ __align__(16) __nv_bfloat16 sAh[64 * FA_STRIDE];
    __shared__ __align__(16) __nv_bfloat16 sAl[64 * FA_STRIDE];
    __shared__ __align__(16) __nv_bfloat16 sB [64 * FB_STRIDE];

    int n0 = blockIdx.x * 128;
    int b  = blockIdx.y;
    int tid = threadIdx.x, wid = tid >> 5, lane = tid & 31;
    int wm = wid >> 2, wn = wid & 3;

    const __nv_bfloat16* gAh = dir ? g_Ahi_h : g_Ahf_h;
    const __nv_bfloat16* gAl = dir ? g_Ahi_l : g_Ahf_l;
    const __nv_bfloat16* Br = (dir ? g_r2 : g_r1) + (size_t)b * H_ * NKC;
    const __nv_bfloat16* Bi = (dir ? g_i2 : g_i1) + (size_t)b * H_ * NKC;
    __nv_bfloat16* Or = g_xr + (size_t)b * H_ * NKC;
    __nv_bfloat16* Oi = g_xi + (size_t)b * H_ * NKC;

    #pragma unroll
    for (int it = 0; it < 4; it++) {
        int lin = tid + 256 * it;
        int r = lin >> 4, cq = (lin & 15) * 4;
        *(uint2*)&sAh[r * FA_STRIDE + cq] = *(const uint2*)&gAh[r * 64 + cq];
        *(uint2*)&sAl[r * FA_STRIDE + cq] = *(const uint2*)&gAl[r * 64 + cq];
    }
    #pragma unroll
    for (int it = 0; it < 4; it++) {
        int lin = tid + 256 * it;
        int r = lin >> 4, cq = (lin & 15) * 8;
        const __nv_bfloat16* src = (r < 32) ? &Br[(size_t)r * NKC + n0 + cq]
                                            : &Bi[(size_t)(r - 32) * NKC + n0 + cq];
        *(uint4*)&sB[r * FB_STRIDE + cq] = *(const uint4*)src;
    }
    __syncthreads();

    float acc[2][4][4] = {};
    int aRow = lane & 15, aK = (lane >> 4) * 8, bK = lane & 15;
    #pragma unroll
    for (int ks = 0; ks < 4; ks++) {
        int k0 = ks * 16;
        uint32_t ah[2][4], al[2][4], bf[4][2];
        #pragma unroll
        for (int i = 0; i < 2; i++) {
            int row = wm * 32 + i * 16 + aRow;
            ldsm_x4(ah[i], smem_u32(&sAh[row * FA_STRIDE + k0 + aK]));
            ldsm_x4(al[i], smem_u32(&sAl[row * FA_STRIDE + k0 + aK]));
        }
        #pragma unroll
        for (int j = 0; j < 4; j++) {
            int nf = wn * 32 + j * 8;
            ldsm_x2_t(bf[j], smem_u32(&sB[(k0 + bK) * FB_STRIDE + nf]));
        }
        #pragma unroll
        for (int i = 0; i < 2; i++)
            #pragma unroll
            for (int j = 0; j < 4; j++) {
                mma_bf16(acc[i][j], ah[i], bf[j]);
                mma_bf16(acc[i][j], al[i], bf[j]);
            }
    }

    int g = lane >> 2, q = (lane & 3) * 2;
    #pragma unroll
    for (int i = 0; i < 2; i++)
        #pragma unroll
        for (int j = 0; j < 4; j++) {
            int row = wm * 32 + i * 16 + g;
            int col = n0 + wn * 32 + j * 8 + q;
            __nv_bfloat16* dst = (row < 32) ? Or + (size_t)row * NKC : Oi + (size_t)(row - 32) * NKC;
            *(uint32_t*)&dst[col]           = pack_bf2(acc[i][j][0], acc[i][j][1]);
            *(uint32_t*)&dst[8 * NKC + col] = pack_bf2(acc[i][j][2], acc[i][j][3]);
        }
}

// ---- W-direction forward DFT: x (fp32) -> g_r1/g_i1 (bf16)
__global__ __launch_bounds__(256) void fft_w_mma(const float* __restrict__ X)
{
    __shared__ __align__(16) __nv_bfloat16 sAh[64 * FA_STRIDE];
    __shared__ __align__(16) __nv_bfloat16 sAl[64 * FA_STRIDE];
    __shared__ __align__(16) __nv_bfloat16 sB [64 * FB_STRIDE];

    int bh = blockIdx.x;
    int c0 = blockIdx.y * 128;
    int tid = threadIdx.x, wid = tid >> 5, lane = tid & 31;
    int wm = wid >> 2, wn = wid & 3;

    #pragma unroll
    for (int it = 0; it < 4; it++) {
        int lin = tid + 256 * it;
        int r = lin >> 4, cq = (lin & 15) * 4;
        *(uint2*)&sAh[r * FA_STRIDE + cq] = *(const uint2*)&g_Awf_h[r * 64 + cq];
        *(uint2*)&sAl[r * FA_STRIDE + cq] = *(const uint2*)&g_Awf_l[r * 64 + cq];
    }
    #pragma unroll
    for (int it = 0; it < 8; it++) {
        int lin = tid + 256 * it;
        int r = lin >> 5, cq = (lin & 31) * 4;
        float4 v = *(const float4*)&X[((size_t)bh * 64 + r) * C_ + c0 + cq];
        __nv_bfloat16 h[4];
        cvt4(v, h);
        *(uint2*)&sB[r * FB_STRIDE + cq] = *(uint2*)h;
    }
    __syncthreads();

    float acc[2][4][4] = {};
    int aRow = lane & 15, aK = (lane >> 4) * 8, bK = lane & 15;
    #pragma unroll
    for (int ks = 0; ks < 4; ks++) {
        int k0 = ks * 16;
        uint32_t ah[2][4], al[2][4], bf[4][2];
        #pragma unroll
        for (int i = 0; i < 2; i++) {
            int row = wm * 32 + i * 16 + aRow;
            ldsm_x4(ah[i], smem_u32(&sAh[row * FA_STRIDE + k0 + aK]));
            ldsm_x4(al[i], smem_u32(&sAl[row * FA_STRIDE + k0 + aK]));
        }
        #pragma unroll
        for (int j = 0; j < 4; j++) {
            int nf = wn * 32 + j * 8;
            ldsm_x2_t(bf[j], smem_u32(&sB[(k0 + bK) * FB_STRIDE + nf]));
        }
        #pragma unroll
        for (int i = 0; i < 2; i++)
            #pragma unroll
            for (int j = 0; j < 4; j++) {
                mma_bf16(acc[i][j], ah[i], bf[j]);
                mma_bf16(acc[i][j], al[i], bf[j]);
            }
    }

    int g = lane >> 2, q = (lane & 3) * 2;
    __nv_bfloat16* Yr = g_r1 + (size_t)bh * WH * C_;
    __nv_bfloat16* Yi = g_i1 + (size_t)bh * WH * C_;
    #pragma unroll
    for (int i = 0; i < 2; i++)
        #pragma unroll
        for (int j = 0; j < 4; j++) {
            int row = wm * 32 + i * 16 + g;
            int col = c0 + wn * 32 + j * 8 + q;
            __nv_bfloat16* dst = (row < 32) ? Yr + (size_t)row * C_ : Yi + (size_t)(row - 32) * C_;
            *(uint32_t*)&dst[col]          = pack_bf2(acc[i][j][0], acc[i][j][1]);
            *(uint32_t*)&dst[8 * C_ + col] = pack_bf2(acc[i][j][2], acc[i][j][3]);
        }

    // Nyquist row k=32: Yr = sum_w (-1)^w x[w], Yi = 0
    if (tid < 128) {
        float alt = 0.f;
        #pragma unroll 8
        for (int w = 0; w < W_; w++) {
            float xv = __bfloat162float(sB[w * FB_STRIDE + tid]);
            alt += (w & 1) ? -xv : xv;
        }
        Yr[(size_t)32 * C_ + c0 + tid] = __float2bfloat16(alt);
        Yi[(size_t)32 * C_ + c0 + tid] = __float2bfloat16(0.f);
    }
}

// ---- W-direction inverse real DFT (MMA): g_xr/g_xi (bf16) -> out (fp32, accumulate)
__global__ __launch_bounds__(256) void fft_w_inv_mma(float* __restrict__ out)
{
    __shared__ __align__(16) __nv_bfloat16 sAh[64 * FA_STRIDE];
    __shared__ __align__(16) __nv_bfloat16 sAl[64 * FA_STRIDE];
    __shared__ __align__(16) __nv_bfloat16 sB [64 * FB_STRIDE];

    int bh = blockIdx.x;
    int c0 = blockIdx.y * 128;
    int tid = threadIdx.x, wid = tid >> 5, lane = tid & 31;
    int wm = wid >> 2, wn = wid & 3;

    const __nv_bfloat16* Fr = g_xr + (size_t)bh * WH * C_;
    const __nv_bfloat16* Fi = g_xi + (size_t)bh * WH * C_;

    #pragma unroll
    for (int it = 0; it < 4; it++) {
        int lin = tid + 256 * it;
        int r = lin >> 4, cq = (lin & 15) * 4;
        *(uint2*)&sAh[r * FA_STRIDE + cq] = *(const uint2*)&g_Awi_h[r * 64 + cq];
        *(uint2*)&sAl[r * FA_STRIDE + cq] = *(const uint2*)&g_Awi_l[r * 64 + cq];
    }
    #pragma unroll
    for (int it = 0; it < 4; it++) {
        int lin = tid + 256 * it;
        int r = lin >> 4, cq = (lin & 15) * 8;
        const __nv_bfloat16* src = (r < 33) ? &Fr[(size_t)r * C_ + c0 + cq]
                                            : &Fi[(size_t)(r - 32) * C_ + c0 + cq];
        *(uint4*)&sB[r * FB_STRIDE + cq] = *(const uint4*)src;
    }
    __syncthreads();

    float acc[2][4][4] = {};
    int aRow = lane & 15, aK = (lane >> 4) * 8, bK = lane & 15;
    #pragma unroll
    for (int ks = 0; ks < 4; ks++) {
        int k0 = ks * 16;
        uint32_t ah[2][4], al[2][4], bf[4][2];
        #pragma unroll
        for (int i = 0; i < 2; i++) {
            int row = wm * 32 + i * 16 + aRow;
            ldsm_x4(ah[i], smem_u32(&sAh[row * FA_STRIDE + k0 + aK]));
            ldsm_x4(al[i], smem_u32(&sAl[row * FA_STRIDE + k0 + aK]));
        }
        #pragma unroll
        for (int j = 0; j < 4; j++) {
            int nf = wn * 32 + j * 8;
            ldsm_x2_t(bf[j], smem_u32(&sB[(k0 + bK) * FB_STRIDE + nf]));
        }
        #pragma unroll
        for (int i = 0; i < 2; i++)
            #pragma unroll
            for (int j = 0; j < 4; j++) {
                mma_bf16(acc[i][j], ah[i], bf[j]);
                mma_bf16(acc[i][j], al[i], bf[j]);
            }
    }

    int g = lane >> 2, q = (lane & 3) * 2;
    float* op = out + (size_t)bh * 64 * C_;
    #pragma unroll
    for (int i = 0; i < 2; i++)
        #pragma unroll
        for (int j = 0; j < 4; j++) {
            int w = wm * 32 + i * 16 + g;
            int col = c0 + wn * 32 + j * 8 + q;
            float* d0 = &op[(size_t)w * C_ + col];
            float* d1 = &op[(size_t)(w + 8) * C_ + col];
            float2 c0v = *(float2*)d0;
            float2 c1v = *(float2*)d1;
            c0v.x += acc[i][j][0]; c0v.y += acc[i][j][1];
            c1v.x += acc[i][j][2]; c1v.y += acc[i][j][3];
            *(float2*)d0 = c0v;
            *(float2*)d1 = c1v;
        }
}

// =====================================================================
// freq MLP via mma.sync, plain bf16 (1-term)
// =====================================================================
#define FM 128
#define FN 64
#define FK 16
#define XPAD (FK + 8)
#define WPAD (FN + 8)

__global__ __launch_bounds__(256) void freq_l1_mma(
    const float* __restrict__ w1, const float* __restrict__ b1)
{
    __shared__ __align__(16) __nv_bfloat16 sXr[FM][XPAD], sXi[FM][XPAD];
    __shared__ __align__(16) __nv_bfloat16 sWr[FK][WPAD], sWi[FK][WPAD], sWn[FK][WPAD];

    int tid = threadIdx.x, wid = tid >> 5, lane = tid & 31;
    int wm = wid >> 2, wn = wid & 3;
    int p0 = blockIdx.x * FM, j0 = blockIdx.y * FN, nb = blockIdx.z;
    const float* Wr = w1 + (size_t)nb * BS_ * BS_;
    const float* Wi = w1 + (size_t)(NBLK + nb) * BS_ * BS_;

    float accR[4][2][4] = {}, accI[4][2][4] = {};
    int aRow = lane & 15, aK = (lane >> 4) * 8;
    int bKrow = lane & 15;

    for (int kt = 0; kt < BS_; kt += FK) {
        {
            int r = tid >> 1, cq = (tid & 1) * 8;
            *(uint4*)&sXr[r][cq] = *(const uint4*)&g_xr[(size_t)(p0 + r) * C_ + nb * BS_ + kt + cq];
            *(uint4*)&sXi[r][cq] = *(const uint4*)&g_xi[(size_t)(p0 + r) * C_ + nb * BS_ + kt + cq];
        }
        {
            int d = tid >> 4, jq = (tid & 15) * 4;
            float4 vr = *(const float4*)&Wr[(size_t)(kt + d) * BS_ + j0 + jq];
            float4 vi = *(const float4*)&Wi[(size_t)(kt + d) * BS_ + j0 + jq];
            __nv_bfloat16 h[4];
            cvt4(vr, h);
            *(uint2*)&sWr[d][jq] = *(uint2*)h;
            cvt4(vi, h);
            *(uint2*)&sWi[d][jq] = *(uint2*)h;
            float4 vn = {-vi.x, -vi.y, -vi.z, -vi.w};
            cvt4(vn, h);
            *(uint2*)&sWn[d][jq] = *(uint2*)h;
        }
        __syncthreads();

        uint32_t axr[4][4], axi[4][4];
        #pragma unroll
        for (int i = 0; i < 4; i++) {
            int row = wm * 64 + i * 16 + aRow;
            ldsm_x4(axr[i], smem_u32(&sXr[row][aK]));
            ldsm_x4(axi[i], smem_u32(&sXi[row][aK]));
        }
        uint32_t bwr[2][2], bwi[2][2], bwn[2][2];
        #pragma unroll
        for (int j = 0; j < 2; j++) {
            int nf = wn * 16 + j * 8;
            ldsm_x2_t(bwr[j], smem_u32(&sWr[bKrow][nf]));
            ldsm_x2_t(bwi[j], smem_u32(&sWi[bKrow][nf]));
            ldsm_x2_t(bwn[j], smem_u32(&sWn[bKrow][nf]));
        }
        #pragma unroll
        for (int i = 0; i < 4; i++)
            #pragma unroll
            for (int j = 0; j < 2; j++) {
                mma_bf16(accR[i][j], axr[i], bwr[j]);
                mma_bf16(accR[i][j], axi[i], bwn[j]);
                mma_bf16(accI[i][j], axr[i], bwi[j]);
                mma_bf16(accI[i][j], axi[i], bwr[j]);
            }
        __syncthreads();
    }

    const float* br = b1 + (size_t)nb * BS_;
    const float* bi = b1 + (size_t)(NBLK + nb) * BS_;
    int g = lane >> 2, q = (lane & 3) * 2;
    #pragma unroll
    for (int i = 0; i < 4; i++)
        #pragma unroll
        for (int j = 0; j < 2; j++) {
            int col = j0 + wn * 16 + j * 8 + q;
            float br0 = br[col], br1 = br[col + 1];
            float bi0 = bi[col], bi1 = bi[col + 1];
            int r0 = p0 + wm * 64 + i * 16 + g;
            size_t o0 = (size_t)r0 * C_ + nb * BS_ + col;
            size_t o1 = (size_t)(r0 + 8) * C_ + nb * BS_ + col;
            *(uint32_t*)&g_r1[o0] = pack_bf2(fmaxf(accR[i][j][0] + br0, 0.f), fmaxf(accR[i][j][1] + br1, 0.f));
            *(uint32_t*)&g_r1[o1] = pack_bf2(fmaxf(accR[i][j][2] + br0, 0.f), fmaxf(accR[i][j][3] + br1, 0.f));
            *(uint32_t*)&g_i1[o0] = pack_bf2(fmaxf(accI[i][j][0] + bi0, 0.f), fmaxf(accI[i][j][1] + bi1, 0.f));
            *(uint32_t*)&g_i1[o1] = pack_bf2(fmaxf(accI[i][j][2] + bi0, 0.f), fmaxf(accI[i][j][3] + bi1, 0.f));
        }
}

__global__ __launch_bounds__(256) void freq_l2_mma(
    const float* __restrict__ w2, const float* __restrict__ b2, int phase)
{
    __shared__ __align__(16) __nv_bfloat16 sA[FM][XPAD], sBm[FM][XPAD];
    __shared__ __align__(16) __nv_bfloat16 sWa[FK][WPAD], sWb[FK][WPAD];

    int tid = threadIdx.x, wid = tid >> 5, lane = tid & 31;
    int wm = wid >> 2, wn = wid & 3;
    int p0 = blockIdx.x * FM, j0 = blockIdx.y * FN, nb = blockIdx.z;

    const __nv_bfloat16* A  = (phase == 0 ? g_r1 : g_r2);
    const __nv_bfloat16* Bm = g_i1;
    const float* Wa = w2 + (size_t)((phase == 0 ? 0 : NBLK) + nb) * BS_ * BS_;
    const float* Wb = w2 + (size_t)((phase == 0 ? NBLK : 0) + nb) * BS_ * BS_;
    const float* bias = b2 + (size_t)(phase == 0 ? 0 : NBLK) * BS_ + (size_t)nb * BS_;
    __nv_bfloat16* O = (phase == 0 ? g_r2 : g_i2);
    float sgn = (phase == 0) ? -1.f : 1.f;

    float acc[4][2][4] = {};
    int aRow = lane & 15, aK = (lane >> 4) * 8;
    int bKrow = lane & 15;

    for (int kt = 0; kt < BS_; kt += FK) {
        {
            int r = tid >> 1, cq = (tid & 1) * 8;
            *(uint4*)&sA [r][cq] = *(const uint4*)&A [(size_t)(p0 + r) * C_ + nb * BS_ + kt + cq];
            *(uint4*)&sBm[r][cq] = *(const uint4*)&Bm[(size_t)(p0 + r) * C_ + nb * BS_ + kt + cq];
        }
        {
            int d = tid >> 4, jq = (tid & 15) * 4;
            float4 va = *(const float4*)&Wa[(size_t)(kt + d) * BS_ + j0 + jq];
            float4 vb = *(const float4*)&Wb[(size_t)(kt + d) * BS_ + j0 + jq];
            vb.x *= sgn; vb.y *= sgn; vb.z *= sgn; vb.w *= sgn;
            __nv_bfloat16 h[4];
            cvt4(va, h);
            *(uint2*)&sWa[d][jq] = *(uint2*)h;
            cvt4(vb, h);
            *(uint2*)&sWb[d][jq] = *(uint2*)h;
        }
        __syncthreads();

        uint32_t aa[4][4], ab[4][4];
        #pragma unroll
        for (int i = 0; i < 4; i++) {
            int row = wm * 64 + i * 16 + aRow;
            ldsm_x4(aa[i], smem_u32(&sA [row][aK]));
            ldsm_x4(ab[i], smem_u32(&sBm[row][aK]));
        }
        uint32_t ba[2][2], bbf[2][2];
        #pragma unroll
        for (int j = 0; j < 2; j++) {
            int nf = wn * 16 + j * 8;
            ldsm_x2_t(ba[j],  smem_u32(&sWa[bKrow][nf]));
            ldsm_x2_t(bbf[j], smem_u32(&sWb[bKrow][nf]));
        }
        #pragma unroll
        for (int i = 0; i < 4; i++)
            #pragma unroll
            for (int j = 0; j < 2; j++) {
                mma_bf16(acc[i][j], aa[i], ba[j]);
                mma_bf16(acc[i][j], ab[i], bbf[j]);
            }
        __syncthreads();
    }

    int g = lane >> 2, q = (lane & 3) * 2;
    #pragma unroll
    for (int i = 0; i < 4; i++)
        #pragma unroll
        for (int j = 0; j < 2; j++) {
            int col = j0 + wn * 16 + j * 8 + q;
            float b0 = bias[col], b1 = bias[col + 1];
            int r0 = p0 + wm * 64 + i * 16 + g;
            size_t o0 = (size_t)r0 * C_ + nb * BS_ + col;
            size_t o1 = (size_t)(r0 + 8) * C_ + nb * BS_ + col;
            *(uint32_t*)&O[o0] = pack_bf2(acc[i][j][0] + b0, acc[i][j][1] + b1);
            *(uint32_t*)&O[o1] = pack_bf2(acc[i][j][2] + b0, acc[i][j][3] + b1);
        }
}

// =====================================================================
extern "C" void kernel_launch(void* const* d_in, const int* in_sizes, int n_in,
                              void* d_out, int out_size)
{
    const float* x  = (const float*)d_in[0];
    const float* w1 = (const float*)d_in[1];
    const float* b1 = (const float*)d_in[2];
    const float* w2 = (const float*)d_in[3];
    const float* b2 = (const float*)d_in[4];
    const float* bw = (const float*)d_in[5];
    const float* bb = (const float*)d_in[6];
    float* out = (float*)d_out;

    cudaFuncSetAttribute(bias_mma, cudaFuncAttributeMaxDynamicSharedMemorySize, 2 * BSTAGE);

    init_tables<<<32, 256>>>();

    convert_xw<<<(NXQ + NWQ + 255) / 256, 256>>>(x, bw);

    bias_mma<<<dim3(C_ / TBN, NTOK / TBM), 256, 2 * BSTAGE>>>(bb, out);

    fft_w_mma<<<dim3(B_ * H_, C_ / 128), 256>>>(x);        // (512, 6)
    fft_h_mma<<<dim3(NKC / 128, B_), 256>>>(0);            // (198, 16)

    dim3 gFreq(P_ / FM, BS_ / FN, NBLK);                   // (132, 3, 4)
    freq_l1_mma<<<gFreq, 256>>>(w1, b1);
    freq_l2_mma<<<gFreq, 256>>>(w2, b2, 0);
    freq_l2_mma<<<gFreq, 256>>>(w2, b2, 1);

    fft_h_mma<<<dim3(NKC / 128, B_), 256>>>(1);            // (198, 16)
    fft_w_inv_mma<<<dim3(B_ * H_, C_ / 128), 256>>>(out);  // (512, 6)
}

// round 17
// speedup vs baseline: 1.5025x; 1.5025x over previous
#include <cuda_runtime.h>
#include <cuda_bf16.h>
#include <cstdint>

// ---------------- problem constants ----------------
#define B_  16
#define H_  32
#define W_  64
#define WH  33            // W/2+1
#define C_  768
#define NBLK 4
#define BS_ 192           // C/NBLK
#define P_  (B_*H_*WH)    // 16896 frequency positions
#define NKC (WH*C_)       // 25344
#define NTOK (B_*H_*W_)   // 32768 spatial tokens

#define SC_ORTHO 0.0220970869120796f   // 1/sqrt(2048)

// ---------------- scratch (bf16 freq-domain data path) ----------------
__device__ __nv_bfloat16 g_xr[(size_t)P_ * C_];
__device__ __nv_bfloat16 g_xi[(size_t)P_ * C_];
__device__ __nv_bfloat16 g_r1[(size_t)P_ * C_];
__device__ __nv_bfloat16 g_i1[(size_t)P_ * C_];
__device__ __nv_bfloat16 g_r2[(size_t)P_ * C_];
__device__ __nv_bfloat16 g_i2[(size_t)P_ * C_];

// pre-split 64x64 DFT operator matrices (bf16 hi/lo)
__device__ __nv_bfloat16 g_Ahf_h[4096], g_Ahf_l[4096];   // H fwd (scaled)
__device__ __nv_bfloat16 g_Ahi_h[4096], g_Ahi_l[4096];   // H inv
__device__ __nv_bfloat16 g_Awf_h[4096], g_Awf_l[4096];   // W fwd (k=0..31)
__device__ __nv_bfloat16 g_Awi_h[4096], g_Awi_l[4096];   // W inv (weights folded)

// =====================================================================
// portable tensor-core helpers
// =====================================================================
__device__ __forceinline__ uint32_t smem_u32(const void* p) {
    uint32_t a;
    asm("{ .reg .u64 t; cvta.to.shared.u64 t, %1; cvt.u32.u64 %0, t; }" : "=r"(a) : "l"(p));
    return a;
}
__device__ __forceinline__ void mma_bf16(float* d, const uint32_t* a, const uint32_t* b) {
    asm volatile("mma.sync.aligned.m16n8k16.row.col.f32.bf16.bf16.f32 "
        "{%0,%1,%2,%3}, {%4,%5,%6,%7}, {%8,%9}, {%0,%1,%2,%3};"
        : "+f"(d[0]), "+f"(d[1]), "+f"(d[2]), "+f"(d[3])
        : "r"(a[0]), "r"(a[1]), "r"(a[2]), "r"(a[3]), "r"(b[0]), "r"(b[1]));
}
__device__ __forceinline__ void ldsm_x4(uint32_t* r, uint32_t addr) {
    asm volatile("ldmatrix.sync.aligned.m8n8.x4.shared.b16 {%0,%1,%2,%3}, [%4];"
        : "=r"(r[0]), "=r"(r[1]), "=r"(r[2]), "=r"(r[3]) : "r"(addr));
}
__device__ __forceinline__ void ldsm_x2(uint32_t* r, uint32_t addr) {
    asm volatile("ldmatrix.sync.aligned.m8n8.x2.shared.b16 {%0,%1}, [%2];"
        : "=r"(r[0]), "=r"(r[1]) : "r"(addr));
}
__device__ __forceinline__ void ldsm_x2_t(uint32_t* r, uint32_t addr) {
    asm volatile("ldmatrix.sync.aligned.m8n8.x2.trans.shared.b16 {%0,%1}, [%2];"
        : "=r"(r[0]), "=r"(r[1]) : "r"(addr));
}
__device__ __forceinline__ void split4(float4 v, __nv_bfloat16* h, __nv_bfloat16* l) {
    float a[4] = {v.x, v.y, v.z, v.w};
    #pragma unroll
    for (int q = 0; q < 4; q++) {
        h[q] = __float2bfloat16(a[q]);
        l[q] = __float2bfloat16(a[q] - __bfloat162float(h[q]));
    }
}
__device__ __forceinline__ void cvt4(float4 v, __nv_bfloat16* h) {
    h[0] = __float2bfloat16(v.x);
    h[1] = __float2bfloat16(v.y);
    h[2] = __float2bfloat16(v.z);
    h[3] = __float2bfloat16(v.w);
}
__device__ __forceinline__ void split1(float v, __nv_bfloat16& h, __nv_bfloat16& l) {
    h = __float2bfloat16(v);
    l = __float2bfloat16(v - __bfloat162float(h));
}
__device__ __forceinline__ uint32_t pack_bf2(float a, float b) {
    __nv_bfloat162 t = __floats2bfloat162_rn(a, b);
    return *(uint32_t*)&t;
}

// =====================================================================
__global__ void init_tables()
{
    int idx = blockIdx.x * blockDim.x + threadIdx.x;
    for (int i = idx; i < 4096; i += gridDim.x * blockDim.x) {
        int r = i >> 6, q = i & 63;
        {
            float s, c;
            sincospif((float)((r & 31) * (q & 31)) / 16.0f, &s, &c);
            float v;
            if (r < 32)  v = (q < 32) ? c : s;
            else         v = (q < 32) ? -s : c;
            split1(v * SC_ORTHO, g_Ahf_h[i], g_Ahf_l[i]);
        }
        {
            float s, c;
            sincospif((float)((r & 31) * (q & 31)) / 16.0f, &s, &c);
            float v;
            if (r < 32)  v = (q < 32) ? c : -s;
            else         v = (q < 32) ? s : c;
            split1(v, g_Ahi_h[i], g_Ahi_l[i]);
        }
        {
            float s, c;
            sincospif((float)((r & 31) * q) / 32.0f, &s, &c);
            float v = (r < 32) ? c : -s;
            split1(v, g_Awf_h[i], g_Awf_l[i]);
        }
        {
            float v;
            if (q == 0) {
                v = SC_ORTHO;
            } else if (q < 32) {
                float s, c;
                sincospif((float)(q * r) / 32.0f, &s, &c);
                v = 2.f * SC_ORTHO * c;
            } else if (q == 32) {
                v = (r & 1) ? -SC_ORTHO : SC_ORTHO;
            } else {
                int k = q - 32;
                float s, c;
                sincospif((float)(k * r) / 32.0f, &s, &c);
                v = -2.f * SC_ORTHO * s;
            }
            split1(v, g_Awi_h[i], g_Awi_l[i]);
        }
    }
}

// =====================================================================
// bias GEMM via mma.sync bf16 split-precision (validated R4/R13 — frozen)
// =====================================================================
#define TBM 128
#define TBN 128
#define TBK 32
#define KPAD (TBK + 8)

__global__ __launch_bounds__(256) void bias_mma(
    const float* __restrict__ X, const float* __restrict__ Wm,
    const float* __restrict__ bb, float* __restrict__ out)
{
    __shared__ __align__(16) __nv_bfloat16 sAhi[TBM][KPAD];
    __shared__ __align__(16) __nv_bfloat16 sAlo[TBM][KPAD];
    __shared__ __align__(16) __nv_bfloat16 sBhi[TBN][KPAD];
    __shared__ __align__(16) __nv_bfloat16 sBlo[TBN][KPAD];

    int tid = threadIdx.x;
    int wid = tid >> 5, lane = tid & 31;
    int wm = wid >> 2, wn = wid & 3;
    int m0 = blockIdx.y * TBM, n0 = blockIdx.x * TBN;

    float acc[4][4][4] = {};

    int aRow = lane & 15, aKoff = (lane >> 4) * 8;
    int bRow = lane & 7,  bKoff = ((lane >> 3) & 1) * 8;

    for (int kt = 0; kt < C_; kt += TBK) {
        #pragma unroll
        for (int it = 0; it < 4; it++) {
            int lin = tid + 256 * it;
            int r = lin >> 3, cq = (lin & 7) * 4;
            float4 va = *(const float4*)&X [(size_t)(m0 + r) * C_ + kt + cq];
            float4 vb = *(const float4*)&Wm[(size_t)(n0 + r) * C_ + kt + cq];
            __nv_bfloat16 ah[4], al[4], bh[4], bl[4];
            split4(va, ah, al);
            split4(vb, bh, bl);
            *(uint2*)&sAhi[r][cq] = *(uint2*)ah;
            *(uint2*)&sAlo[r][cq] = *(uint2*)al;
            *(uint2*)&sBhi[r][cq] = *(uint2*)bh;
            *(uint2*)&sBlo[r][cq] = *(uint2*)bl;
        }
        __syncthreads();

        #pragma unroll
        for (int s = 0; s < 2; s++) {
            int k0 = s * 16;
            uint32_t a_hi[4][4], a_lo[4][4], b_hi[4][2], b_lo[4][2];
            #pragma unroll
            for (int i = 0; i < 4; i++) {
                int row = wm * 64 + i * 16 + aRow;
                ldsm_x4(a_hi[i], smem_u32(&sAhi[row][k0 + aKoff]));
                ldsm_x4(a_lo[i], smem_u32(&sAlo[row][k0 + aKoff]));
            }
            #pragma unroll
            for (int j = 0; j < 4; j++) {
                int row = wn * 32 + j * 8 + bRow;
                ldsm_x2(b_hi[j], smem_u32(&sBhi[row][k0 + bKoff]));
                ldsm_x2(b_lo[j], smem_u32(&sBlo[row][k0 + bKoff]));
            }
            #pragma unroll
            for (int i = 0; i < 4; i++)
                #pragma unroll
                for (int j = 0; j < 4; j++) {
                    mma_bf16(acc[i][j], a_hi[i], b_hi[j]);
                    mma_bf16(acc[i][j], a_hi[i], b_lo[j]);
                    mma_bf16(acc[i][j], a_lo[i], b_hi[j]);
                }
        }
        __syncthreads();
    }

    int group = lane >> 2, qid = lane & 3;
    #pragma unroll
    for (int i = 0; i < 4; i++) {
        #pragma unroll
        for (int j = 0; j < 4; j++) {
            int col = n0 + wn * 32 + j * 8 + qid * 2;
            float b0 = bb[col], b1 = bb[col + 1];
            int r0 = m0 + wm * 64 + i * 16 + group;
            float2 v0 = {acc[i][j][0] + b0, acc[i][j][1] + b1};
            float2 v1 = {acc[i][j][2] + b0, acc[i][j][3] + b1};
            *(float2*)&out[(size_t)r0 * C_ + col]       = v0;
            *(float2*)&out[(size_t)(r0 + 8) * C_ + col] = v1;
        }
    }
}

// =====================================================================
// FFT-as-GEMM kernels: C[64, N] = A(64x64, split 2-term) @ B[64, N] (bf16)
// =====================================================================
#define FA_STRIDE 72
#define FB_STRIDE 136

// ---- H-direction DFT (dir 0 = fwd g_r1/g_i1 -> g_xr/g_xi, dir 1 = inv g_r2/g_i2 -> g_xr/g_xi)
__global__ __launch_bounds__(256) void fft_h_mma(int dir)
{
    __shared__ __align__(16) __nv_bfloat16 sAh[64 * FA_STRIDE];
    __shared__ __align__(16) __nv_bfloat16 sAl[64 * FA_STRIDE];
    __shared__ __align__(16) __nv_bfloat16 sB [64 * FB_STRIDE];

    int n0 = blockIdx.x * 128;
    int b  = blockIdx.y;
    int tid = threadIdx.x, wid = tid >> 5, lane = tid & 31;
    int wm = wid >> 2, wn = wid & 3;

    const __nv_bfloat16* gAh = dir ? g_Ahi_h : g_Ahf_h;
    const __nv_bfloat16* gAl = dir ? g_Ahi_l : g_Ahf_l;
    const __nv_bfloat16* Br = (dir ? g_r2 : g_r1) + (size_t)b * H_ * NKC;
    const __nv_bfloat16* Bi = (dir ? g_i2 : g_i1) + (size_t)b * H_ * NKC;
    __nv_bfloat16* Or = g_xr + (size_t)b * H_ * NKC;
    __nv_bfloat16* Oi = g_xi + (size_t)b * H_ * NKC;

    #pragma unroll
    for (int it = 0; it < 4; it++) {
        int lin = tid + 256 * it;
        int r = lin >> 4, cq = (lin & 15) * 4;
        *(uint2*)&sAh[r * FA_STRIDE + cq] = *(const uint2*)&gAh[r * 64 + cq];
        *(uint2*)&sAl[r * FA_STRIDE + cq] = *(const uint2*)&gAl[r * 64 + cq];
    }
    #pragma unroll
    for (int it = 0; it < 4; it++) {
        int lin = tid + 256 * it;
        int r = lin >> 4, cq = (lin & 15) * 8;
        const __nv_bfloat16* src = (r < 32) ? &Br[(size_t)r * NKC + n0 + cq]
                                            : &Bi[(size_t)(r - 32) * NKC + n0 + cq];
        *(uint4*)&sB[r * FB_STRIDE + cq] = *(const uint4*)src;
    }
    __syncthreads();

    float acc[2][4][4] = {};
    int aRow = lane & 15, aK = (lane >> 4) * 8, bK = lane & 15;
    #pragma unroll
    for (int ks = 0; ks < 4; ks++) {
        int k0 = ks * 16;
        uint32_t ah[2][4], al[2][4], bf[4][2];
        #pragma unroll
        for (int i = 0; i < 2; i++) {
            int row = wm * 32 + i * 16 + aRow;
            ldsm_x4(ah[i], smem_u32(&sAh[row * FA_STRIDE + k0 + aK]));
            ldsm_x4(al[i], smem_u32(&sAl[row * FA_STRIDE + k0 + aK]));
        }
        #pragma unroll
        for (int j = 0; j < 4; j++) {
            int nf = wn * 32 + j * 8;
            ldsm_x2_t(bf[j], smem_u32(&sB[(k0 + bK) * FB_STRIDE + nf]));
        }
        #pragma unroll
        for (int i = 0; i < 2; i++)
            #pragma unroll
            for (int j = 0; j < 4; j++) {
                mma_bf16(acc[i][j], ah[i], bf[j]);
                mma_bf16(acc[i][j], al[i], bf[j]);
            }
    }

    int g = lane >> 2, q = (lane & 3) * 2;
    #pragma unroll
    for (int i = 0; i < 2; i++)
        #pragma unroll
        for (int j = 0; j < 4; j++) {
            int row = wm * 32 + i * 16 + g;
            int col = n0 + wn * 32 + j * 8 + q;
            __nv_bfloat16* dst = (row < 32) ? Or + (size_t)row * NKC : Oi + (size_t)(row - 32) * NKC;
            *(uint32_t*)&dst[col]           = pack_bf2(acc[i][j][0], acc[i][j][1]);
            *(uint32_t*)&dst[8 * NKC + col] = pack_bf2(acc[i][j][2], acc[i][j][3]);
        }
}

// ---- W-direction forward DFT: x (fp32) -> g_r1/g_i1 (bf16)
__global__ __launch_bounds__(256) void fft_w_mma(const float* __restrict__ X)
{
    __shared__ __align__(16) __nv_bfloat16 sAh[64 * FA_STRIDE];
    __shared__ __align__(16) __nv_bfloat16 sAl[64 * FA_STRIDE];
    __shared__ __align__(16) __nv_bfloat16 sB [64 * FB_STRIDE];

    int bh = blockIdx.x;
    int c0 = blockIdx.y * 128;
    int tid = threadIdx.x, wid = tid >> 5, lane = tid & 31;
    int wm = wid >> 2, wn = wid & 3;

    #pragma unroll
    for (int it = 0; it < 4; it++) {
        int lin = tid + 256 * it;
        int r = lin >> 4, cq = (lin & 15) * 4;
        *(uint2*)&sAh[r * FA_STRIDE + cq] = *(const uint2*)&g_Awf_h[r * 64 + cq];
        *(uint2*)&sAl[r * FA_STRIDE + cq] = *(const uint2*)&g_Awf_l[r * 64 + cq];
    }
    #pragma unroll
    for (int it = 0; it < 8; it++) {
        int lin = tid + 256 * it;
        int r = lin >> 5, cq = (lin & 31) * 4;
        float4 v = *(const float4*)&X[((size_t)bh * 64 + r) * C_ + c0 + cq];
        __nv_bfloat16 h[4];
        cvt4(v, h);
        *(uint2*)&sB[r * FB_STRIDE + cq] = *(uint2*)h;
    }
    __syncthreads();

    float acc[2][4][4] = {};
    int aRow = lane & 15, aK = (lane >> 4) * 8, bK = lane & 15;
    #pragma unroll
    for (int ks = 0; ks < 4; ks++) {
        int k0 = ks * 16;
        uint32_t ah[2][4], al[2][4], bf[4][2];
        #pragma unroll
        for (int i = 0; i < 2; i++) {
            int row = wm * 32 + i * 16 + aRow;
            ldsm_x4(ah[i], smem_u32(&sAh[row * FA_STRIDE + k0 + aK]));
            ldsm_x4(al[i], smem_u32(&sAl[row * FA_STRIDE + k0 + aK]));
        }
        #pragma unroll
        for (int j = 0; j < 4; j++) {
            int nf = wn * 32 + j * 8;
            ldsm_x2_t(bf[j], smem_u32(&sB[(k0 + bK) * FB_STRIDE + nf]));
        }
        #pragma unroll
        for (int i = 0; i < 2; i++)
            #pragma unroll
            for (int j = 0; j < 4; j++) {
                mma_bf16(acc[i][j], ah[i], bf[j]);
                mma_bf16(acc[i][j], al[i], bf[j]);
            }
    }

    int g = lane >> 2, q = (lane & 3) * 2;
    __nv_bfloat16* Yr = g_r1 + (size_t)bh * WH * C_;
    __nv_bfloat16* Yi = g_i1 + (size_t)bh * WH * C_;
    #pragma unroll
    for (int i = 0; i < 2; i++)
        #pragma unroll
        for (int j = 0; j < 4; j++) {
            int row = wm * 32 + i * 16 + g;
            int col = c0 + wn * 32 + j * 8 + q;
            __nv_bfloat16* dst = (row < 32) ? Yr + (size_t)row * C_ : Yi + (size_t)(row - 32) * C_;
            *(uint32_t*)&dst[col]          = pack_bf2(acc[i][j][0], acc[i][j][1]);
            *(uint32_t*)&dst[8 * C_ + col] = pack_bf2(acc[i][j][2], acc[i][j][3]);
        }

    // Nyquist row k=32: Yr = sum_w (-1)^w x[w], Yi = 0.
    // Parallel over all 256 threads: 2 threads per channel, shfl combine.
    {
        int c = tid >> 1, half = tid & 1;
        float alt = 0.f;
        int w0 = half * 32;
        #pragma unroll 8
        for (int w = w0; w < w0 + 32; w++) {
            float xv = __bfloat162float(sB[w * FB_STRIDE + c]);
            alt += (w & 1) ? -xv : xv;
        }
        alt += __shfl_xor_sync(0xFFFFFFFF, alt, 1);
        if (half == 0)
            Yr[(size_t)32 * C_ + c0 + c] = __float2bfloat16(alt);
        else
            Yi[(size_t)32 * C_ + c0 + c] = __float2bfloat16(0.f);
    }
}

// ---- W-direction inverse real DFT (MMA): g_xr/g_xi (bf16) -> out (fp32, accumulate)
__global__ __launch_bounds__(256) void fft_w_inv_mma(float* __restrict__ out)
{
    __shared__ __align__(16) __nv_bfloat16 sAh[64 * FA_STRIDE];
    __shared__ __align__(16) __nv_bfloat16 sAl[64 * FA_STRIDE];
    __shared__ __align__(16) __nv_bfloat16 sB [64 * FB_STRIDE];

    int bh = blockIdx.x;
    int c0 = blockIdx.y * 128;
    int tid = threadIdx.x, wid = tid >> 5, lane = tid & 31;
    int wm = wid >> 2, wn = wid & 3;

    const __nv_bfloat16* Fr = g_xr + (size_t)bh * WH * C_;
    const __nv_bfloat16* Fi = g_xi + (size_t)bh * WH * C_;

    #pragma unroll
    for (int it = 0; it < 4; it++) {
        int lin = tid + 256 * it;
        int r = lin >> 4, cq = (lin & 15) * 4;
        *(uint2*)&sAh[r * FA_STRIDE + cq] = *(const uint2*)&g_Awi_h[r * 64 + cq];
        *(uint2*)&sAl[r * FA_STRIDE + cq] = *(const uint2*)&g_Awi_l[r * 64 + cq];
    }
    #pragma unroll
    for (int it = 0; it < 4; it++) {
        int lin = tid + 256 * it;
        int r = lin >> 4, cq = (lin & 15) * 8;
        const __nv_bfloat16* src = (r < 33) ? &Fr[(size_t)r * C_ + c0 + cq]
                                            : &Fi[(size_t)(r - 32) * C_ + c0 + cq];
        *(uint4*)&sB[r * FB_STRIDE + cq] = *(const uint4*)src;
    }
    __syncthreads();

    float acc[2][4][4] = {};
    int aRow = lane & 15, aK = (lane >> 4) * 8, bK = lane & 15;
    #pragma unroll
    for (int ks = 0; ks < 4; ks++) {
        int k0 = ks * 16;
        uint32_t ah[2][4], al[2][4], bf[4][2];
        #pragma unroll
        for (int i = 0; i < 2; i++) {
            int row = wm * 32 + i * 16 + aRow;
            ldsm_x4(ah[i], smem_u32(&sAh[row * FA_STRIDE + k0 + aK]));
            ldsm_x4(al[i], smem_u32(&sAl[row * FA_STRIDE + k0 + aK]));
        }
        #pragma unroll
        for (int j = 0; j < 4; j++) {
            int nf = wn * 32 + j * 8;
            ldsm_x2_t(bf[j], smem_u32(&sB[(k0 + bK) * FB_STRIDE + nf]));
        }
        #pragma unroll
        for (int i = 0; i < 2; i++)
            #pragma unroll
            for (int j = 0; j < 4; j++) {
                mma_bf16(acc[i][j], ah[i], bf[j]);
                mma_bf16(acc[i][j], al[i], bf[j]);
            }
    }

    int g = lane >> 2, q = (lane & 3) * 2;
    float* op = out + (size_t)bh * 64 * C_;
    #pragma unroll
    for (int i = 0; i < 2; i++)
        #pragma unroll
        for (int j = 0; j < 4; j++) {
            int w = wm * 32 + i * 16 + g;
            int col = c0 + wn * 32 + j * 8 + q;
            float* d0 = &op[(size_t)w * C_ + col];
            float* d1 = &op[(size_t)(w + 8) * C_ + col];
            float2 c0v = *(float2*)d0;
            float2 c1v = *(float2*)d1;
            c0v.x += acc[i][j][0]; c0v.y += acc[i][j][1];
            c1v.x += acc[i][j][2]; c1v.y += acc[i][j][3];
            *(float2*)d0 = c0v;
            *(float2*)d1 = c1v;
        }
}

// =====================================================================
// freq MLP via mma.sync, plain bf16 (1-term), FK=32 (6 outer iters)
// =====================================================================
#define FM 128
#define FN 64
#define FK 32
#define XPAD (FK + 8)     // 40 halfs = 80B stride (proven conflict-free)
#define WPAD (FN + 8)

__global__ __launch_bounds__(256) void freq_l1_mma(
    const float* __restrict__ w1, const float* __restrict__ b1)
{
    __shared__ __align__(16) __nv_bfloat16 sXr[FM][XPAD], sXi[FM][XPAD];
    __shared__ __align__(16) __nv_bfloat16 sWr[FK][WPAD], sWi[FK][WPAD], sWn[FK][WPAD];

    int tid = threadIdx.x, wid = tid >> 5, lane = tid & 31;
    int wm = wid >> 2, wn = wid & 3;
    int p0 = blockIdx.x * FM, j0 = blockIdx.y * FN, nb = blockIdx.z;
    const float* Wr = w1 + (size_t)nb * BS_ * BS_;
    const float* Wi = w1 + (size_t)(NBLK + nb) * BS_ * BS_;

    float accR[4][2][4] = {}, accI[4][2][4] = {};
    int aRow = lane & 15, aK = (lane >> 4) * 8;
    int bKrow = lane & 15;

    for (int kt = 0; kt < BS_; kt += FK) {
        // X fill: 128 rows x 32 cols, 8 bf16 per chunk -> 512 chunks, 2/thread
        #pragma unroll
        for (int it = 0; it < 2; it++) {
            int lin = tid + 256 * it;
            int r = lin >> 2, cq = (lin & 3) * 8;
            *(uint4*)&sXr[r][cq] = *(const uint4*)&g_xr[(size_t)(p0 + r) * C_ + nb * BS_ + kt + cq];
            *(uint4*)&sXi[r][cq] = *(const uint4*)&g_xi[(size_t)(p0 + r) * C_ + nb * BS_ + kt + cq];
        }
        // W fill: 32 rows x 64 cols fp32 -> 512 float4 quads, 2/thread
        #pragma unroll
        for (int it = 0; it < 2; it++) {
            int lin = tid + 256 * it;
            int d = lin >> 4, jq = (lin & 15) * 4;
            float4 vr = *(const float4*)&Wr[(size_t)(kt + d) * BS_ + j0 + jq];
            float4 vi = *(const float4*)&Wi[(size_t)(kt + d) * BS_ + j0 + jq];
            __nv_bfloat16 h[4];
            cvt4(vr, h);
            *(uint2*)&sWr[d][jq] = *(uint2*)h;
            cvt4(vi, h);
            *(uint2*)&sWi[d][jq] = *(uint2*)h;
            float4 vn = {-vi.x, -vi.y, -vi.z, -vi.w};
            cvt4(vn, h);
            *(uint2*)&sWn[d][jq] = *(uint2*)h;
        }
        __syncthreads();

        #pragma unroll
        for (int ks = 0; ks < 2; ks++) {
            int k0 = ks * 16;
            uint32_t axr[4][4], axi[4][4];
            #pragma unroll
            for (int i = 0; i < 4; i++) {
                int row = wm * 64 + i * 16 + aRow;
                ldsm_x4(axr[i], smem_u32(&sXr[row][k0 + aK]));
                ldsm_x4(axi[i], smem_u32(&sXi[row][k0 + aK]));
            }
            uint32_t bwr[2][2], bwi[2][2], bwn[2][2];
            #pragma unroll
            for (int j = 0; j < 2; j++) {
                int nf = wn * 16 + j * 8;
                ldsm_x2_t(bwr[j], smem_u32(&sWr[k0 + bKrow][nf]));
                ldsm_x2_t(bwi[j], smem_u32(&sWi[k0 + bKrow][nf]));
                ldsm_x2_t(bwn[j], smem_u32(&sWn[k0 + bKrow][nf]));
            }
            #pragma unroll
            for (int i = 0; i < 4; i++)
                #pragma unroll
                for (int j = 0; j < 2; j++) {
                    mma_bf16(accR[i][j], axr[i], bwr[j]);
                    mma_bf16(accR[i][j], axi[i], bwn[j]);
                    mma_bf16(accI[i][j], axr[i], bwi[j]);
                    mma_bf16(accI[i][j], axi[i], bwr[j]);
                }
        }
        __syncthreads();
    }

    const float* br = b1 + (size_t)nb * BS_;
    const float* bi = b1 + (size_t)(NBLK + nb) * BS_;
    int g = lane >> 2, q = (lane & 3) * 2;
    #pragma unroll
    for (int i = 0; i < 4; i++)
        #pragma unroll
        for (int j = 0; j < 2; j++) {
            int col = j0 + wn * 16 + j * 8 + q;
            float br0 = br[col], br1 = br[col + 1];
            float bi0 = bi[col], bi1 = bi[col + 1];
            int r0 = p0 + wm * 64 + i * 16 + g;
            size_t o0 = (size_t)r0 * C_ + nb * BS_ + col;
            size_t o1 = (size_t)(r0 + 8) * C_ + nb * BS_ + col;
            *(uint32_t*)&g_r1[o0] = pack_bf2(fmaxf(accR[i][j][0] + br0, 0.f), fmaxf(accR[i][j][1] + br1, 0.f));
            *(uint32_t*)&g_r1[o1] = pack_bf2(fmaxf(accR[i][j][2] + br0, 0.f), fmaxf(accR[i][j][3] + br1, 0.f));
            *(uint32_t*)&g_i1[o0] = pack_bf2(fmaxf(accI[i][j][0] + bi0, 0.f), fmaxf(accI[i][j][1] + bi1, 0.f));
            *(uint32_t*)&g_i1[o1] = pack_bf2(fmaxf(accI[i][j][2] + bi0, 0.f), fmaxf(accI[i][j][3] + bi1, 0.f));
        }
}

__global__ __launch_bounds__(256) void freq_l2_mma(
    const float* __restrict__ w2, const float* __restrict__ b2, int phase)
{
    __shared__ __align__(16) __nv_bfloat16 sA[FM][XPAD], sBm[FM][XPAD];
    __shared__ __align__(16) __nv_bfloat16 sWa[FK][WPAD], sWb[FK][WPAD];

    int tid = threadIdx.x, wid = tid >> 5, lane = tid & 31;
    int wm = wid >> 2, wn = wid & 3;
    int p0 = blockIdx.x * FM, j0 = blockIdx.y * FN, nb = blockIdx.z;

    const __nv_bfloat16* A  = (phase == 0 ? g_r1 : g_r2);
    const __nv_bfloat16* Bm = g_i1;
    const float* Wa = w2 + (size_t)((phase == 0 ? 0 : NBLK) + nb) * BS_ * BS_;
    const float* Wb = w2 + (size_t)((phase == 0 ? NBLK : 0) + nb) * BS_ * BS_;
    const float* bias = b2 + (size_t)(phase == 0 ? 0 : NBLK) * BS_ + (size_t)nb * BS_;
    __nv_bfloat16* O = (phase == 0 ? g_r2 : g_i2);
    float sgn = (phase == 0) ? -1.f : 1.f;

    float acc[4][2][4] = {};
    int aRow = lane & 15, aK = (lane >> 4) * 8;
    int bKrow = lane & 15;

    for (int kt = 0; kt < BS_; kt += FK) {
        #pragma unroll
        for (int it = 0; it < 2; it++) {
            int lin = tid + 256 * it;
            int r = lin >> 2, cq = (lin & 3) * 8;
            *(uint4*)&sA [r][cq] = *(const uint4*)&A [(size_t)(p0 + r) * C_ + nb * BS_ + kt + cq];
            *(uint4*)&sBm[r][cq] = *(const uint4*)&Bm[(size_t)(p0 + r) * C_ + nb * BS_ + kt + cq];
        }
        #pragma unroll
        for (int it = 0; it < 2; it++) {
            int lin = tid + 256 * it;
            int d = lin >> 4, jq = (lin & 15) * 4;
            float4 va = *(const float4*)&Wa[(size_t)(kt + d) * BS_ + j0 + jq];
            float4 vb = *(const float4*)&Wb[(size_t)(kt + d) * BS_ + j0 + jq];
            vb.x *= sgn; vb.y *= sgn; vb.z *= sgn; vb.w *= sgn;
            __nv_bfloat16 h[4];
            cvt4(va, h);
            *(uint2*)&sWa[d][jq] = *(uint2*)h;
            cvt4(vb, h);
            *(uint2*)&sWb[d][jq] = *(uint2*)h;
        }
        __syncthreads();

        #pragma unroll
        for (int ks = 0; ks < 2; ks++) {
            int k0 = ks * 16;
            uint32_t aa[4][4], ab[4][4];
            #pragma unroll
            for (int i = 0; i < 4; i++) {
                int row = wm * 64 + i * 16 + aRow;
                ldsm_x4(aa[i], smem_u32(&sA [row][k0 + aK]));
                ldsm_x4(ab[i], smem_u32(&sBm[row][k0 + aK]));
            }
            uint32_t ba[2][2], bbf[2][2];
            #pragma unroll
            for (int j = 0; j < 2; j++) {
                int nf = wn * 16 + j * 8;
                ldsm_x2_t(ba[j],  smem_u32(&sWa[k0 + bKrow][nf]));
                ldsm_x2_t(bbf[j], smem_u32(&sWb[k0 + bKrow][nf]));
            }
            #pragma unroll
            for (int i = 0; i < 4; i++)
                #pragma unroll
                for (int j = 0; j < 2; j++) {
                    mma_bf16(acc[i][j], aa[i], ba[j]);
                    mma_bf16(acc[i][j], ab[i], bbf[j]);
                }
        }
        __syncthreads();
    }

    int g = lane >> 2, q = (lane & 3) * 2;
    #pragma unroll
    for (int i = 0; i < 4; i++)
        #pragma unroll
        for (int j = 0; j < 2; j++) {
            int col = j0 + wn * 16 + j * 8 + q;
            float b0 = bias[col], b1 = bias[col + 1];
            int r0 = p0 + wm * 64 + i * 16 + g;
            size_t o0 = (size_t)r0 * C_ + nb * BS_ + col;
            size_t o1 = (size_t)(r0 + 8) * C_ + nb * BS_ + col;
            *(uint32_t*)&O[o0] = pack_bf2(acc[i][j][0] + b0, acc[i][j][1] + b1);
            *(uint32_t*)&O[o1] = pack_bf2(acc[i][j][2] + b0, acc[i][j][3] + b1);
        }
}

// =====================================================================
extern "C" void kernel_launch(void* const* d_in, const int* in_sizes, int n_in,
                              void* d_out, int out_size)
{
    const float* x  = (const float*)d_in[0];
    const float* w1 = (const float*)d_in[1];
    const float* b1 = (const float*)d_in[2];
    const float* w2 = (const float*)d_in[3];
    const float* b2 = (const float*)d_in[4];
    const float* bw = (const float*)d_in[5];
    const float* bb = (const float*)d_in[6];
    float* out = (float*)d_out;

    init_tables<<<32, 256>>>();

    bias_mma<<<dim3(C_ / TBN, NTOK / TBM), 256>>>(x, bw, bb, out);

    fft_w_mma<<<dim3(B_ * H_, C_ / 128), 256>>>(x);        // (512, 6)
    fft_h_mma<<<dim3(NKC / 128, B_), 256>>>(0);            // (198, 16)

    dim3 gFreq(P_ / FM, BS_ / FN, NBLK);                   // (132, 3, 4)
    freq_l1_mma<<<gFreq, 256>>>(w1, b1);
    freq_l2_mma<<<gFreq, 256>>>(w2, b2, 0);
    freq_l2_mma<<<gFreq, 256>>>(w2, b2, 1);

    fft_h_mma<<<dim3(NKC / 128, B_), 256>>>(1);            // (198, 16)
    fft_w_inv_mma<<<dim3(B_ * H_, C_ / 128), 256>>>(out);  // (512, 6)
}